// round 5
// baseline (speedup 1.0000x reference)
#include <cuda_runtime.h>
#include <cstdint>

// Problem constants: N=100000, E=3200000, B=512, F_X=64, F_U=128, F_OUT=128.
#define MAXN   100000
#define MAXE   3400000
#define MAXB   1024
#define FX     64
#define FU     128
#define FOUT   128

__device__ float g_agg[(size_t)MAXN * FX];    // aggregated node feats [N, FX]
__device__ float g_c[(size_t)MAXB * 256];     // per-batch u@W_bot + b, both halves
__device__ int   g_flags[2];                  // [0]=edge_index int64, [1]=batch int64
__device__ uint4 g_rec[MAXE];                 // sorted edge records {src, dst, a, 0}
__device__ int   g_cnt[MAXN + 1024];          // per-dest counts
__device__ int   g_ptr[MAXN + 1024];          // per-dest running offsets
__device__ int   g_bsum[(MAXN + 1023) / 1024 + 2];

// ---------------------------------------------------------------------------
__device__ __forceinline__ void red_add_v2(float* addr, float2 v) {
    asm volatile("red.global.add.v2.f32 [%0], {%1,%2};"
                 :: "l"(addr), "f"(v.x), "f"(v.y) : "memory");
}

__device__ __forceinline__ uint32_t f2tf32(float f) {
    uint32_t r;
    asm("cvt.rna.tf32.f32 %0, %1;" : "=r"(r) : "f"(f));
    return r;
}

__device__ __forceinline__ void mma_tf32(float* c, const uint32_t* a,
                                         const uint32_t* b) {
    asm volatile(
        "mma.sync.aligned.m16n8k8.row.col.f32.tf32.tf32.f32 "
        "{%0,%1,%2,%3}, {%4,%5,%6,%7}, {%8,%9}, {%0,%1,%2,%3};"
        : "+f"(c[0]), "+f"(c[1]), "+f"(c[2]), "+f"(c[3])
        : "r"(a[0]), "r"(a[1]), "r"(a[2]), "r"(a[3]), "r"(b[0]), "r"(b[1]));
}

// ---------------------------------------------------------------------------
// Kernel 0: dtype detection (int64 vs int32)
// ---------------------------------------------------------------------------
__global__ void detect_kernel(const int* __restrict__ ei,
                              const int* __restrict__ batch,
                              int E, int N) {
    __shared__ int s0, s1;
    if (threadIdx.x == 0) { s0 = 1; s1 = 1; }
    __syncthreads();
    int t = threadIdx.x;
    long long k = ((long long)t * 12497 + 1) % E;
    if (ei[2 * k + 1] != 0) s0 = 0;
    if (t < 64) {
        int lo = N / 4, hi = N / 2;
        int step = (hi - lo) / 64; if (step < 1) step = 1;
        long long kb = lo + (long long)t * step;
        if (kb >= hi) kb = hi - 1;
        if (batch[2 * kb + 1] != 0) s1 = 0;
    }
    __syncthreads();
    if (threadIdx.x == 0) { g_flags[0] = s0; g_flags[1] = s1; }
}

// ---------------------------------------------------------------------------
// Zeroing kernels
// ---------------------------------------------------------------------------
__global__ void zero_agg_kernel(long n4) {
    long i = (long)blockIdx.x * blockDim.x + threadIdx.x;
    if (i < n4) ((float4*)g_agg)[i] = make_float4(0.f, 0.f, 0.f, 0.f);
}
__global__ void zero_cnt_kernel(int n) {
    int i = blockIdx.x * blockDim.x + threadIdx.x;
    if (i < n) g_cnt[i] = 0;
}

// ---------------------------------------------------------------------------
// Counting sort by dest: hist -> scan(3) -> reorder
// ---------------------------------------------------------------------------
__global__ void hist_kernel(const int* __restrict__ ei, int E) {
    int e = blockIdx.x * blockDim.x + threadIdx.x;
    if (e >= E) return;
    int dst = g_flags[0] ? (int)((const long long*)ei)[e + E] : ei[e + E];
    atomicAdd(&g_cnt[dst], 1);
}

__global__ void scan1_kernel(int N) {
    __shared__ int s[1024];
    int t = threadIdx.x;
    int i = blockIdx.x * 1024 + t;
    int v = (i < N) ? g_cnt[i] : 0;
    s[t] = v;
    __syncthreads();
    #pragma unroll
    for (int d = 1; d < 1024; d <<= 1) {
        int w = (t >= d) ? s[t - d] : 0;
        __syncthreads();
        s[t] += w;
        __syncthreads();
    }
    if (i < N) g_ptr[i] = s[t] - v;            // block-local exclusive
    if (t == 1023) g_bsum[blockIdx.x] = s[t];  // block total
}

__global__ void scan2_kernel(int nb) {
    __shared__ int s[1024];
    int t = threadIdx.x;
    int v = (t < nb) ? g_bsum[t] : 0;
    s[t] = v;
    __syncthreads();
    #pragma unroll
    for (int d = 1; d < 1024; d <<= 1) {
        int w = (t >= d) ? s[t - d] : 0;
        __syncthreads();
        s[t] += w;
        __syncthreads();
    }
    if (t < nb) g_bsum[t] = s[t] - v;          // exclusive block offsets
}

__global__ void scan3_kernel(int N) {
    int i = blockIdx.x * blockDim.x + threadIdx.x;
    if (i < N) g_ptr[i] += g_bsum[i >> 10];
}

__global__ void reorder_kernel(const int* __restrict__ ei,
                               const float* __restrict__ ea, int E) {
    int e = blockIdx.x * blockDim.x + threadIdx.x;
    if (e >= E) return;
    int src, dst;
    if (g_flags[0]) {
        const long long* p = (const long long*)ei;
        src = (int)p[e];
        dst = (int)p[e + E];
    } else {
        src = ei[e];
        dst = ei[e + E];
    }
    int pos = atomicAdd(&g_ptr[dst], 1);
    g_rec[pos] = make_uint4((unsigned)src, (unsigned)dst,
                            __float_as_uint(ea[e]), 0u);
}

// ---------------------------------------------------------------------------
// Segmented scatter: warp walks a contiguous chunk of dest-sorted edges,
// accumulates a*x[src] in registers (lane owns float2), one red per dest run.
// ---------------------------------------------------------------------------
#define CH 256
__global__ __launch_bounds__(256)
void segscatter_kernel(const float* __restrict__ x, int E) {
    long gw   = ((long)blockIdx.x * blockDim.x + threadIdx.x) >> 5;
    int  lane = threadIdx.x & 31;
    long e0 = gw * CH;
    if (e0 >= E) return;
    long e1 = e0 + CH; if (e1 > E) e1 = E;

    const float2* x2 = (const float2*)x;
    float2 acc = make_float2(0.f, 0.f);
    int prev = -1;

    // one-stage software pipeline: prefetch record + x row
    uint4  rec = g_rec[e0];
    float2 xv  = x2[(size_t)rec.x * 32 + lane];

    for (long e = e0; e < e1; e++) {
        uint4  nrec;
        float2 nxv;
        if (e + 1 < e1) {
            nrec = g_rec[e + 1];
            nxv  = x2[(size_t)nrec.x * 32 + lane];
        }
        int dst = (int)rec.y;
        if (dst != prev) {
            if (prev >= 0)
                red_add_v2(&g_agg[(size_t)prev * FX + lane * 2], acc);
            acc = make_float2(0.f, 0.f);
            prev = dst;
        }
        float a = __uint_as_float(rec.z);
        acc.x = fmaf(a, xv.x, acc.x);
        acc.y = fmaf(a, xv.y, acc.y);
        rec = nrec;
        xv  = nxv;
    }
    if (prev >= 0)
        red_add_v2(&g_agg[(size_t)prev * FX + lane * 2], acc);
}

// ---------------------------------------------------------------------------
// u-term GEMM (exact fp32): one block per (b, half)  [R2 shape — 12.4 us]
// ---------------------------------------------------------------------------
__global__ void ugemm_kernel(const float* __restrict__ u,
                             const float* __restrict__ WK, const float* __restrict__ bK,
                             const float* __restrict__ WQ, const float* __restrict__ bQ) {
    int j    = threadIdx.x;
    int b    = blockIdx.x;
    int half = blockIdx.y;
    const float* W    = half ? WQ : WK;
    const float* bias = half ? bQ : bK;
    const float* urow = u + (size_t)b * FU;
    float acc = bias[j];
    #pragma unroll 8
    for (int k = 0; k < FU; k++)
        acc = fmaf(urow[k], W[(size_t)(FX + k) * FOUT + j], acc);
    g_c[(size_t)b * 256 + half * FOUT + j] = acc;
}

// ---------------------------------------------------------------------------
// tf32 mma.sync GEMM (unchanged from R4 — passed at rel_err 2.7e-4)
// ---------------------------------------------------------------------------
#define ASTRIDE 68
#define SMEM_A_FLOATS (128 * ASTRIDE)
#define GEMM_SMEM_BYTES (2 * SMEM_A_FLOATS * 4 + 512)

__global__ __launch_bounds__(256)
void gemm_tc_kernel(const int*   __restrict__ batch,
                    const float* __restrict__ WK,
                    const float* __restrict__ WQ,
                    float* __restrict__ out, int N) {
    extern __shared__ uint32_t sm[];
    uint32_t* A_s = sm;
    uint32_t* B_s = sm + SMEM_A_FLOATS;
    int* sb = (int*)(sm + 2 * SMEM_A_FLOATS);

    const int tid  = threadIdx.x;
    const int wid  = tid >> 5;
    const int lane = tid & 31;
    const int grp  = lane >> 2;
    const int tig  = lane & 3;
    const int wm   = wid & 3;
    const int wn   = wid >> 2;
    const int row0 = blockIdx.x * 128;
    const int half = blockIdx.y;

    const float* W = half ? WQ : WK;
    float* outbase = out + (size_t)half * N * FOUT;

    const int b_is64 = g_flags[1];
    if (tid < 128) {
        int gr = row0 + tid;
        int b = 0;
        if (gr < N)
            b = b_is64 ? (int)((const long long*)batch)[gr] : batch[gr];
        sb[tid] = b;
    }

    #pragma unroll
    for (int it = 0; it < 8; it++) {
        int f  = it * 256 + tid;
        int r  = f >> 4;
        int q  = f & 15;
        int gr = row0 + r;
        float4 v = make_float4(0.f, 0.f, 0.f, 0.f);
        if (gr < N) v = ((const float4*)g_agg)[(size_t)gr * 16 + q];
        uint4 w;
        w.x = f2tf32(v.x); w.y = f2tf32(v.y);
        w.z = f2tf32(v.z); w.w = f2tf32(v.w);
        *(uint4*)(A_s + r * ASTRIDE + q * 4) = w;
    }

    #pragma unroll
    for (int it = 0; it < 32; it++) {
        int f = it * 256 + tid;
        int k = f >> 7;
        int n = f & 127;
        B_s[n * ASTRIDE + k] = f2tf32(W[(size_t)k * FOUT + n]);
    }
    __syncthreads();

    float acc[2][8][4];
    #pragma unroll
    for (int mi = 0; mi < 2; mi++)
        #pragma unroll
        for (int ni = 0; ni < 8; ni++)
            #pragma unroll
            for (int q = 0; q < 4; q++) acc[mi][ni][q] = 0.f;

    #pragma unroll
    for (int ks = 0; ks < 8; ks++) {
        const int k0 = ks * 8;
        uint32_t a[2][4];
        #pragma unroll
        for (int mi = 0; mi < 2; mi++) {
            int r = wm * 32 + mi * 16 + grp;
            a[mi][0] = A_s[(r    ) * ASTRIDE + k0 + tig    ];
            a[mi][1] = A_s[(r + 8) * ASTRIDE + k0 + tig    ];
            a[mi][2] = A_s[(r    ) * ASTRIDE + k0 + tig + 4];
            a[mi][3] = A_s[(r + 8) * ASTRIDE + k0 + tig + 4];
        }
        uint32_t b[8][2];
        #pragma unroll
        for (int ni = 0; ni < 8; ni++) {
            int n = wn * 64 + ni * 8 + grp;
            b[ni][0] = B_s[n * ASTRIDE + k0 + tig    ];
            b[ni][1] = B_s[n * ASTRIDE + k0 + tig + 4];
        }
        #pragma unroll
        for (int mi = 0; mi < 2; mi++)
            #pragma unroll
            for (int ni = 0; ni < 8; ni++)
                mma_tf32(acc[mi][ni], a[mi], b[ni]);
    }

    #pragma unroll
    for (int mi = 0; mi < 2; mi++) {
        #pragma unroll
        for (int rr = 0; rr < 2; rr++) {
            int r  = wm * 32 + mi * 16 + grp + rr * 8;
            int gr = row0 + r;
            if (gr < N) {
                const float* crow = &g_c[(size_t)sb[r] * 256 + half * FOUT];
                float* orow = outbase + (size_t)gr * FOUT;
                #pragma unroll
                for (int ni = 0; ni < 8; ni++) {
                    int col = wn * 64 + ni * 8 + tig * 2;
                    float2 c = *(const float2*)(crow + col);
                    float2 o;
                    o.x = acc[mi][ni][rr * 2 + 0] + c.x;
                    o.y = acc[mi][ni][rr * 2 + 1] + c.y;
                    *(float2*)(orow + col) = o;
                }
            }
        }
    }
}

// ---------------------------------------------------------------------------
extern "C" void kernel_launch(void* const* d_in, const int* in_sizes, int n_in,
                              void* d_out, int out_size) {
    const float* x     = (const float*)d_in[0];
    const int*   ei    = (const int*)  d_in[1];
    const float* eattr = (const float*)d_in[2];
    const float* u     = (const float*)d_in[3];
    const int*   batch = (const int*)  d_in[4];
    const float* WK    = (const float*)d_in[5];
    const float* bK    = (const float*)d_in[6];
    const float* WQ    = (const float*)d_in[7];
    const float* bQ    = (const float*)d_in[8];
    float* out = (float*)d_out;

    const int E = in_sizes[2];
    const int N = in_sizes[0] / FX;
    const int B = in_sizes[3] / FU;
    const int nb = (N + 1023) / 1024;

    detect_kernel<<<1, 256>>>(ei, batch, E, N);

    long n4 = (long)N * FX / 4;
    zero_agg_kernel<<<(unsigned)((n4 + 255) / 256), 256>>>(n4);
    zero_cnt_kernel<<<(N + 255) / 256, 256>>>(N);

    hist_kernel<<<(E + 255) / 256, 256>>>(ei, E);
    scan1_kernel<<<nb, 1024>>>(N);
    scan2_kernel<<<1, 1024>>>(nb);
    scan3_kernel<<<(N + 255) / 256, 256>>>(N);
    reorder_kernel<<<(E + 255) / 256, 256>>>(ei, eattr, E);

    long nwarp = ((long)E + CH - 1) / CH;
    segscatter_kernel<<<(unsigned)((nwarp * 32 + 255) / 256), 256>>>(x, E);

    dim3 gu(B, 2);
    ugemm_kernel<<<gu, 128>>>(u, WK, bK, WQ, bQ);

    cudaFuncSetAttribute(gemm_tc_kernel,
                         cudaFuncAttributeMaxDynamicSharedMemorySize,
                         GEMM_SMEM_BYTES);
    dim3 g((N + 127) / 128, 2);
    gemm_tc_kernel<<<g, 256, GEMM_SMEM_BYTES>>>(batch, WK, WQ, out, N);
}